// round 14
// baseline (speedup 1.0000x reference)
#include <cuda_runtime.h>
#include <cuda_bf16.h>
#include <math.h>
#include <stdint.h>

// ---------------- problem constants ----------------
#define Bsz 2
#define Sq  256
#define Dm  1024
#define Hh  8
#define HDm 128
#define Ll  16
#define FFd 2048
#define Vv  50257
#define SB  (Sq*Bsz)       // 512 rows, row r = s*Bsz + b  ([S,B,*] layout)
#define SBD (SB*Dm)        // 524288
#define ATT_SCALE 0.08838834764831843f

// ---------------- device scratch (static allocations only) -----------------
__device__ float g_x[SBD];
__device__ float g_q[SBD];
__device__ float g_k[Ll*SBD];
__device__ float g_v[Ll*SBD];
__device__ float g_scores[Ll*16*Sq*Sq];
__device__ float g_comb[SBD];
__device__ float g_res[SBD];
__device__ float g_p2[SBD];
__device__ float g_sp[SBD];
__device__ float g_h[SB*FFd];
__device__ float g_lo[Ll*SBD];

// bf16 3-way splits of transposed W (q,k,v) : [l][mat][n][k]
#define WT_ELEMS (3*Ll*Dm*Dm)
__device__ __align__(256) __nv_bfloat16 g_wt0[WT_ELEMS];
__device__ __align__(256) __nv_bfloat16 g_wt1[WT_ELEMS];
__device__ __align__(256) __nv_bfloat16 g_wt2[WT_ELEMS];
// bf16 3-way splits of activations: slot 0 = embed x, slot 1+j = lo[j]
#define AC_ELEMS ((Ll+1)*SBD)
__device__ __align__(256) __nv_bfloat16 g_ac0[AC_ELEMS];
__device__ __align__(256) __nv_bfloat16 g_ac1[AC_ELEMS];
__device__ __align__(256) __nv_bfloat16 g_ac2[AC_ELEMS];

// ---------------- helpers ----------------------------------------------------
__device__ __forceinline__ uint32_t smem_u32(const void* p){
    uint32_t a;
    asm("{ .reg .u64 t; cvta.to.shared.u64 t, %1; cvt.u32.u64 %0, t; }"
        : "=r"(a) : "l"(p));
    return a;
}

#define LDSM4(r0,r1,r2,r3, addr) \
    asm volatile("ldmatrix.sync.aligned.m8n8.x4.shared.b16 {%0,%1,%2,%3}, [%4];" \
        : "=r"(r0), "=r"(r1), "=r"(r2), "=r"(r3) : "r"(addr))

__device__ __forceinline__ void mma_bf16(float* c, const uint32_t* a,
                                         uint32_t b0, uint32_t b1){
    asm volatile("mma.sync.aligned.m16n8k16.row.col.f32.bf16.bf16.f32 "
        "{%0,%1,%2,%3}, {%4,%5,%6,%7}, {%8,%9}, {%0,%1,%2,%3};"
        : "+f"(c[0]), "+f"(c[1]), "+f"(c[2]), "+f"(c[3])
        : "r"(a[0]), "r"(a[1]), "r"(a[2]), "r"(a[3]), "r"(b0), "r"(b1));
}

// ---------------- HMMA Q/K/V projection (bf16x3 fp32 emulation) --------------
// C[SB,Dm] = act[SB,Dm] @ W  with W^T pre-split in g_wt*.
// CTA tile 128(M) x 64(N); 8 warps (2 M x 4 N); K chunks of 16, double buffer.
// smem layout per stage (27648 B): A splits 3 x [128][24] bf16 (6144 B each),
// then B splits 3 x [64][24] bf16 (3072 B each). Two stages = 55296 B dynamic.
#define KVQ_SMEM 55296

__global__ void k_kvq_mma(const float* __restrict__ bq, const float* __restrict__ bk,
                          const float* __restrict__ bv, int l, int n_eff)
{
    extern __shared__ __align__(128) char smem[];
    const int tid = threadIdx.x, wid = tid >> 5, lane = tid & 31;
    const int warpM = wid & 1, warpN = wid >> 1;
    const int m0 = blockIdx.y << 7, n0 = blockIdx.x << 6;

    // decode z: which matrix / source / output
    int z = blockIdx.z, mat, slot, j;
    const float* bias; float* C;
    if (z == 2*n_eff) { mat = 0; slot = (l==0)?0:l; bias = bq; C = g_q; }
    else if (z < n_eff) {
        mat = 1; j = z; slot = (j==0)?((l==0)?0:l):j; bias = bk;
        C = g_k + (size_t)j*SBD;
    } else {
        mat = 2; j = z - n_eff; slot = (j==0)?((l==0)?0:l):j; bias = bv;
        C = g_v + (size_t)j*SBD;
    }
    const size_t aoff = (size_t)slot*SBD;
    const size_t woff = ((size_t)(l*3+mat))<<20;
    const __nv_bfloat16* Ag[3] = { g_ac0+aoff, g_ac1+aoff, g_ac2+aoff };
    const __nv_bfloat16* Bg[3] = { g_wt0+woff, g_wt1+woff, g_wt2+woff };

    const uint32_t sbase = smem_u32(smem);
    // ldmatrix per-lane offset within a tile: row (lane&15), col-half (lane>>4)*8
    const uint32_t aln = (uint32_t)((lane & 15) * 48 + (lane >> 4) * 16);

    float acc[4][2][4];
#pragma unroll
    for (int mi=0;mi<4;mi++)
#pragma unroll
        for (int nj=0;nj<2;nj++)
#pragma unroll
            for (int e=0;e<4;e++) acc[mi][nj][e] = 0.f;

#define STAGE_KC(kcv, st) do { \
    const int rowA = tid >> 1, koA = (tid & 1) << 3; \
    _Pragma("unroll") \
    for (int s=0;s<3;s++){ \
        *(uint4*)(smem + (st)*27648 + s*6144 + rowA*48 + koA*2) = \
            *(const uint4*)(Ag[s] + (size_t)(m0+rowA)*Dm + (kcv)*16 + koA); \
    } \
    if (tid < 128){ \
        const int rowB = tid >> 1, koB = (tid & 1) << 3; \
        _Pragma("unroll") \
        for (int s=0;s<3;s++){ \
            *(uint4*)(smem + (st)*27648 + 18432 + s*3072 + rowB*48 + koB*2) = \
                *(const uint4*)(Bg[s] + (size_t)(n0+rowB)*Dm + (kcv)*16 + koB); \
        } \
    } \
} while(0)

    STAGE_KC(0, 0);
    __syncthreads();

    const int NBL[3] = {3, 2, 1};   // b-splits used per a-split group
    for (int kc = 0; kc < 64; kc++){
        const int st = kc & 1;
        if (kc + 1 < 64) STAGE_KC(kc + 1, st ^ 1);

        const uint32_t sb0 = sbase + st*27648;
        // B fragments: all 3 splits, x4 each (n 0-15 x k 0-15 of this warp)
        uint32_t Bf[3][4];
#pragma unroll
        for (int s=0;s<3;s++){
            uint32_t addr = sb0 + 18432 + s*3072 + (uint32_t)(warpN*16)*48 + aln;
            LDSM4(Bf[s][0], Bf[s][1], Bf[s][2], Bf[s][3], addr);
        }
        // A groups
#pragma unroll
        for (int g=0; g<3; g++){
            uint32_t Af[4][4];
#pragma unroll
            for (int mi=0;mi<4;mi++){
                uint32_t addr = sb0 + g*6144
                              + (uint32_t)(warpM*64 + mi*16)*48 + aln;
                LDSM4(Af[mi][0], Af[mi][1], Af[mi][2], Af[mi][3], addr);
            }
#pragma unroll
            for (int bidx=0; bidx<3; bidx++){
                if (bidx >= NBL[g]) break;
#pragma unroll
                for (int mi=0;mi<4;mi++){
                    mma_bf16(acc[mi][0], Af[mi], Bf[bidx][0], Bf[bidx][2]);
                    mma_bf16(acc[mi][1], Af[mi], Bf[bidx][1], Bf[bidx][3]);
                }
            }
        }
        __syncthreads();
    }

    // epilogue: d-frag (m16n8): c0,c1 -> row lane>>2, cols (lane&3)*2 +{0,1};
    // c2,c3 -> row +8
    const int rbase = m0 + warpM*64 + (lane >> 2);
    const int cbase = n0 + warpN*16 + ((lane & 3) << 1);
#pragma unroll
    for (int mi=0;mi<4;mi++){
#pragma unroll
        for (int nj=0;nj<2;nj++){
            const float* c = acc[mi][nj];
            int r = rbase + mi*16;
            int cc = cbase + nj*8;
            float b0v = bias[cc], b1v = bias[cc+1];
            C[(size_t)r*Dm + cc]       = c[0] + b0v;
            C[(size_t)r*Dm + cc + 1]   = c[1] + b1v;
            C[(size_t)(r+8)*Dm + cc]   = c[2] + b0v;
            C[(size_t)(r+8)*Dm + cc+1] = c[3] + b1v;
        }
    }
#undef STAGE_KC
}

// ------- weight transpose + 3-way bf16 split (once per launch) --------------
__global__ void k_convW(const float* __restrict__ Wq, const float* __restrict__ Wk,
                        const float* __restrict__ Wv)
{
    __shared__ float t[32][33];
    int z = blockIdx.z, l = z/3, m = z%3;
    const float* W = (m==0?Wq:(m==1?Wk:Wv)) + ((size_t)l<<20);
    int k = blockIdx.y*32 + threadIdx.y;
    int n = blockIdx.x*32 + threadIdx.x;
    t[threadIdx.y][threadIdx.x] = W[(size_t)k*Dm + n];
    __syncthreads();
    float v = t[threadIdx.x][threadIdx.y];
    size_t o = (((size_t)z)<<20) + (size_t)(blockIdx.x*32+threadIdx.y)*Dm
             + blockIdx.y*32 + threadIdx.x;
    __nv_bfloat16 h0 = __float2bfloat16(v);
    float r1 = v - __bfloat162float(h0);
    __nv_bfloat16 h1 = __float2bfloat16(r1);
    float r2 = r1 - __bfloat162float(h1);
    g_wt0[o] = h0; g_wt1[o] = h1; g_wt2[o] = __float2bfloat16(r2);
}

__device__ __forceinline__ void split3(float v, size_t o){
    __nv_bfloat16 h0 = __float2bfloat16(v);
    float r1 = v - __bfloat162float(h0);
    __nv_bfloat16 h1 = __float2bfloat16(r1);
    float r2 = r1 - __bfloat162float(h1);
    g_ac0[o] = h0; g_ac1[o] = h1; g_ac2[o] = __float2bfloat16(r2);
}

// ---------------- fp32 scalar GEMM path ----------------
__device__ __forceinline__ float4 ldg4_guard(const float* p, int col, int N)
{
    float4 r;
    if (col + 3 < N && ((((size_t)p) & 15) == 0)) {
        r = *(const float4*)(p);
    } else {
        r.x = (col+0<N)? p[0]:0.f; r.y = (col+1<N)? p[1]:0.f;
        r.z = (col+2<N)? p[2]:0.f; r.w = (col+3<N)? p[3]:0.f;
    }
    return r;
}
#define LDK 68
#define MM16F(Abuf, Bbuf) \
  _Pragma("unroll") \
  for (int kk=0;kk<16;kk++){ \
    float4 a4 = *(const float4*)&Abuf[kk][ty<<2]; \
    float4 b4 = *(const float4*)&Bbuf[kk][tx<<2]; \
    acc[0][0]=fmaf(a4.x,b4.x,acc[0][0]); acc[0][1]=fmaf(a4.x,b4.y,acc[0][1]); \
    acc[0][2]=fmaf(a4.x,b4.z,acc[0][2]); acc[0][3]=fmaf(a4.x,b4.w,acc[0][3]); \
    acc[1][0]=fmaf(a4.y,b4.x,acc[1][0]); acc[1][1]=fmaf(a4.y,b4.y,acc[1][1]); \
    acc[1][2]=fmaf(a4.y,b4.z,acc[1][2]); acc[1][3]=fmaf(a4.y,b4.w,acc[1][3]); \
    acc[2][0]=fmaf(a4.z,b4.x,acc[2][0]); acc[2][1]=fmaf(a4.z,b4.y,acc[2][1]); \
    acc[2][2]=fmaf(a4.z,b4.z,acc[2][2]); acc[2][3]=fmaf(a4.z,b4.w,acc[2][3]); \
    acc[3][0]=fmaf(a4.w,b4.x,acc[3][0]); acc[3][1]=fmaf(a4.w,b4.y,acc[3][1]); \
    acc[3][2]=fmaf(a4.w,b4.z,acc[3][2]); acc[3][3]=fmaf(a4.w,b4.w,acc[3][3]); \
  }
#define STAGE_T(T, buf, v) \
  T[buf][acol+0][arow]=v.x; T[buf][acol+1][arow]=v.y; \
  T[buf][acol+2][arow]=v.z; T[buf][acol+3][arow]=v.w;
#define STAGE_K(T, buf, v) *(float4*)&T[buf][brow][bcol] = v;

__device__ __forceinline__ void gemm_core(
    const float* __restrict__ A, int lda, const float* __restrict__ Bw,
    const float* __restrict__ bias, const float* __restrict__ res,
    float* __restrict__ C, int N, int Kred, int relu, int store_T)
{
    __shared__ __align__(16) float As[2][16][LDK];
    __shared__ __align__(16) float Bs[2][16][LDK];
    const int tid = threadIdx.x;
    const int tx = tid & 15, ty = tid >> 4;
    const int m0 = blockIdx.y << 6, n0 = blockIdx.x << 6;
    const int arow = tid >> 2, acol = (tid & 3) << 2;
    const int brow = tid >> 4, bcol = (tid & 15) << 2;
    float acc[4][4];
#pragma unroll
    for (int i=0;i<4;i++)
#pragma unroll
        for (int j=0;j<4;j++) acc[i][j]=0.f;

    const float* Ap = A + (size_t)(m0 + arow) * lda + acol;
    const int nk = Kred >> 4;
    float4 aR, bR;

    aR = *(const float4*)(Ap);
    bR = ldg4_guard(Bw + (size_t)brow * N + n0 + bcol, n0 + bcol, N);
    STAGE_T(As, 0, aR); STAGE_K(Bs, 0, bR);
    __syncthreads();

    for (int kt = 1; kt < nk; kt++) {
        aR = *(const float4*)(Ap + kt*16);
        bR = ldg4_guard(Bw + (size_t)(kt*16 + brow) * N + n0 + bcol, n0 + bcol, N);
        const int cb = (kt-1)&1, nb = kt&1;
        MM16F(As[cb], Bs[cb]);
        STAGE_T(As, nb, aR); STAGE_K(Bs, nb, bR);
        __syncthreads();
    }
    { const int lb = (nk-1)&1; MM16F(As[lb], Bs[lb]); }

#pragma unroll
    for (int i=0;i<4;i++){
        int m = m0 + (ty<<2) + i;
#pragma unroll
        for (int j=0;j<4;j++){
            int nn = n0 + (tx<<2) + j;
            if (nn >= N) continue;
            float v = acc[i][j];
            if (bias) v += bias[nn];
            if (res)  v += res[(size_t)m*N + nn];
            if (relu) v = fmaxf(v, 0.f);
            if (!store_T) {
                C[(size_t)m*N + nn] = v;
            } else {
                int s = m >> 1, b = m & 1;
                C[(size_t)(b*Sq + s)*N + nn] = v;
            }
        }
    }
}

__global__ void k_gemm(const float* __restrict__ A, const float* __restrict__ Bw,
                       const float* __restrict__ bias, const float* __restrict__ res,
                       float* __restrict__ C, int N, int K, int relu, int store_T)
{
    gemm_core(A, K, Bw, bias, res, C, N, K, relu, store_T);
}

__global__ void k_gemm_sk(const float* __restrict__ A, const float* __restrict__ Bw,
                          const float* __restrict__ bias, const float* __restrict__ res,
                          float* __restrict__ C0, float* __restrict__ C1, int N, int K)
{
    const int z = blockIdx.z;
    const int Kh = K >> 1;
    gemm_core(A + (size_t)z*Kh, K, Bw + (size_t)z*Kh*N,
              z ? nullptr : bias, z ? nullptr : res,
              z ? C1 : C0, N, Kh, 0, 0);
}

// ---------------- embedding + positional encoding (+ splits slot 0) ---------
__global__ void k_embed(const int* __restrict__ src, const float* __restrict__ emb)
{
    int idx = blockIdx.x * 256 + threadIdx.x;
    int d = idx & (Dm-1);
    int r = idx >> 10;
    int b = r & 1, s = r >> 1;
    int tok = src[b*Sq + s];
    float v = emb[(size_t)tok*Dm + d] * 32.0f;
    int de = d & ~1;
    float ang = (float)s * expf((float)de * -0.008994473019508f);
    float pe = (d & 1) ? cosf(ang) : sinf(ang);
    float val = v + pe;
    g_x[idx] = val;
    split3(val, (size_t)idx);
}

// ---------------- scores: per (source j, head bh) NT-GEMM -------------------
__global__ void k_scores(int n_eff)
{
    __shared__ __align__(16) float Qs[2][16][LDK];
    __shared__ __align__(16) float Ks[2][16][LDK];
    const int tid = threadIdx.x;
    const int tx = tid & 15, ty = tid >> 4;
    const int arow = tid >> 2, acol = (tid & 3) << 2;
    const int z = blockIdx.z;
    const int bh = z & 15;
    const int b = bh >> 3, h = bh & 7;
    const int LDX = Bsz * Dm;
    const float* Aq = g_q + b*Dm + h*HDm;
    const float* Bk = g_k + (size_t)(z >> 4)*SBD + b*Dm + h*HDm;
    float* C = g_scores + (size_t)z * Sq * Sq;
    const int m0 = blockIdx.y << 6, n0 = blockIdx.x << 6;
    float acc[4][4];
#pragma unroll
    for (int i=0;i<4;i++)
#pragma unroll
        for (int j=0;j<4;j++) acc[i][j]=0.f;

    const float* Ap = Aq + (size_t)(m0 + arow) * LDX + acol;
    const float* Bp = Bk + (size_t)(n0 + arow) * LDX + acol;
    float4 qR, kR;

    qR = *(const float4*)(Ap);
    kR = *(const float4*)(Bp);
    STAGE_T(Qs, 0, qR); STAGE_T(Ks, 0, kR);
    __syncthreads();

    for (int kt = 1; kt < 8; kt++) {
        qR = *(const float4*)(Ap + kt*16);
        kR = *(const float4*)(Bp + kt*16);
        const int cb = (kt-1)&1, nb = kt&1;
        MM16F(Qs[cb], Ks[cb]);
        STAGE_T(Qs, nb, qR); STAGE_T(Ks, nb, kR);
        __syncthreads();
    }
    MM16F(Qs[1], Ks[1]);

#pragma unroll
    for (int i=0;i<4;i++){
        int m = m0 + (ty<<2) + i;
#pragma unroll
        for (int j=0;j<4;j++){
            int nn = n0 + (tx<<2) + j;
            C[(size_t)m*Sq + nn] = acc[i][j] * ATT_SCALE;
        }
    }
}

// ------- softmax over keys x layer weight (dedup merged weight) -------------
__global__ void k_softmax(const float* __restrict__ lw, int n, int n_eff)
{
    int row  = blockIdx.x * 8 + (threadIdx.x >> 5);
    int lane = threadIdx.x & 31;
    float* p = g_scores + (size_t)row * Sq;
    float x[8];
#pragma unroll
    for (int i=0;i<8;i++) x[i] = p[lane + (i<<5)];
    float mx = x[0];
#pragma unroll
    for (int i=1;i<8;i++) mx = fmaxf(mx, x[i]);
#pragma unroll
    for (int off=16;off>0;off>>=1) mx = fmaxf(mx, __shfl_xor_sync(0xffffffffu, mx, off));
    float sum = 0.f;
#pragma unroll
    for (int i=0;i<8;i++){ x[i] = expf(x[i]-mx); sum += x[i]; }
#pragma unroll
    for (int off=16;off>0;off>>=1) sum += __shfl_xor_sync(0xffffffffu, sum, off);
    int jj = row >> 12;
    float lm = -1e30f;
    for (int t=0;t<n;t++) lm = fmaxf(lm, lw[t]);
    float ls = 0.f;
    for (int t=0;t<n;t++) ls += expf(lw[t]-lm);
    float wj = expf(lw[jj]-lm) / ls;
    if (n > n_eff && jj == 0) wj += expf(lw[n-1]-lm) / ls;
    float sc = wj / sum;
#pragma unroll
    for (int i=0;i<8;i++) p[lane + (i<<5)] = x[i] * sc;
}

// ---------------- comb: per head, sum over sources j of attn_j @ v_j --------
__global__ void k_comb(int n_eff)
{
    __shared__ __align__(16) float As[2][16][LDK];
    __shared__ __align__(16) float Bs[2][16][LDK];
    const int tid = threadIdx.x;
    const int tx = tid & 15, ty = tid >> 4;
    const int arow = tid >> 2, acol = (tid & 3) << 2;
    const int brow = tid >> 4, bcol = (tid & 15) << 2;
    const int bh = blockIdx.z, b = bh >> 3, h = bh & 7;
    const int m0 = blockIdx.y << 6, n0 = blockIdx.x << 6;
    float acc[4][4];
#pragma unroll
    for (int i=0;i<4;i++)
#pragma unroll
        for (int j=0;j<4;j++) acc[i][j]=0.f;

    for (int j=0;j<n_eff;j++){
        const float* Aj = g_scores + (size_t)(j*16 + bh) * Sq * Sq;
        const float* Vj = g_v + (size_t)j*SBD + b*Dm + h*HDm;
        const float* Ap = Aj + (size_t)(m0 + arow) * Sq + acol;
        float4 aR, bR;
        aR = *(const float4*)(Ap);
        bR = *(const float4*)(Vj + (size_t)brow*2048 + n0 + bcol);
        STAGE_T(As, 0, aR); STAGE_K(Bs, 0, bR);
        __syncthreads();
        for (int kt = 1; kt < 16; kt++) {
            aR = *(const float4*)(Ap + kt*16);
            bR = *(const float4*)(Vj + (size_t)(kt*16+brow)*2048 + n0 + bcol);
            const int cb = (kt-1)&1, nb = kt&1;
            MM16F(As[cb], Bs[cb]);
            STAGE_T(As, nb, aR); STAGE_K(Bs, nb, bR);
            __syncthreads();
        }
        MM16F(As[1], Bs[1]);
        __syncthreads();
    }

#pragma unroll
    for (int i=0;i<4;i++){
        int q = m0 + (ty<<2) + i;
        int r = q*Bsz + b;
#pragma unroll
        for (int j=0;j<4;j++){
            int d = h*HDm + n0 + (tx<<2) + j;
            g_comb[(size_t)r*Dm + d] = acc[i][j];
        }
    }
}

// ------- layernorm over D of (in [+ in2]); optional copy + bf16 splits ------
__global__ void k_ln(const float* __restrict__ in, const float* __restrict__ in2,
                     const float* __restrict__ g, const float* __restrict__ be,
                     float* __restrict__ out, float* __restrict__ out2, int acslot)
{
    __shared__ float s1[8], s2[8];
    __shared__ float smean, srstd;
    int r = blockIdx.x, tid = threadIdx.x;
    int lane = tid & 31, wid = tid >> 5;
    const float* row  = in  + (size_t)r*Dm;
    const float* row2 = in2 ? in2 + (size_t)r*Dm : nullptr;
    float v[4], sum = 0.f, sq = 0.f;
#pragma unroll
    for (int i=0;i<4;i++){
        float t = row[tid + (i<<8)];
        if (row2) t += row2[tid + (i<<8)];
        v[i] = t; sum += t; sq += t*t;
    }
#pragma unroll
    for (int off=16;off>0;off>>=1){
        sum += __shfl_xor_sync(0xffffffffu, sum, off);
        sq  += __shfl_xor_sync(0xffffffffu, sq,  off);
    }
    if (lane == 0){ s1[wid] = sum; s2[wid] = sq; }
    __syncthreads();
    if (tid == 0){
        float a=0.f, c=0.f;
        for (int i=0;i<8;i++){ a += s1[i]; c += s2[i]; }
        float mean = a * (1.f/1024.f);
        float var  = c * (1.f/1024.f) - mean*mean;
        smean = mean; srstd = rsqrtf(var + 1e-5f);
    }
    __syncthreads();
    float mean = smean, rstd = srstd;
#pragma unroll
    for (int i=0;i<4;i++){
        int d = tid + (i<<8);
        float o = (v[i]-mean)*rstd*g[d] + be[d];
        out[(size_t)r*Dm + d] = o;
        if (out2) out2[(size_t)r*Dm + d] = o;
        if (acslot >= 0) split3(o, (size_t)acslot*SBD + (size_t)r*Dm + d);
    }
}

// ---------------- SNN scan ---------------------------------------------------
__global__ void k_snn(const float* __restrict__ cur, const float* __restrict__ cur2,
                      float* __restrict__ sp)
{
    __shared__ float red[32];
    __shared__ float redt;
    int b = blockIdx.x, d = threadIdx.x;
    int lane = d & 31, wid = d >> 5;
    float mem = 0.f, thr = 1.0f;
    size_t i0 = (size_t)b*Dm + d;
    float nxt = cur[i0] + cur2[i0];
    for (int t=0;t<Sq;t++){
        float cin = nxt;
        if (t+1 < Sq){
            size_t ix = (size_t)((t+1)*Bsz + b)*Dm + d;
            nxt = cur[ix] + cur2[ix];
        }
        float v = mem;
#pragma unroll
        for (int off=16;off>0;off>>=1) v += __shfl_xor_sync(0xffffffffu, v, off);
        if (lane == 0) red[wid] = v;
        __syncthreads();
        if (wid == 0){
            float u = red[lane];
#pragma unroll
            for (int off=16;off>0;off>>=1) u += __shfl_xor_sync(0xffffffffu, u, off);
            if (lane == 0) redt = u;
        }
        __syncthreads();
        float c = cin - 0.1f * redt;
        mem = 0.9f * mem + c;
        float s = (mem >= thr) ? 1.f : 0.f;
        mem -= s * thr;
        thr = 0.9f * thr + 0.1f * s;
        sp[(size_t)(t*Bsz + b)*Dm + d] = s;
    }
}

// ---------------- host orchestration ----------------------------------------
extern "C" void kernel_launch(void* const* d_in, const int* in_sizes, int n_in,
                              void* d_out, int out_size)
{
    const int*   src  = (const int*)  d_in[0];
    const float* emb  = (const float*)d_in[1];
    const float* Wq   = (const float*)d_in[2];
    const float* bq   = (const float*)d_in[3];
    const float* Wk   = (const float*)d_in[4];
    const float* bk   = (const float*)d_in[5];
    const float* Wv   = (const float*)d_in[6];
    const float* bv   = (const float*)d_in[7];
    const float* Wo   = (const float*)d_in[8];
    const float* bo   = (const float*)d_in[9];
    const float* layer_w = (const float*)d_in[10];
    const float* Wsnn = (const float*)d_in[11];
    const float* bsnn = (const float*)d_in[12];
    const float* W1   = (const float*)d_in[13];
    const float* b1   = (const float*)d_in[14];
    const float* W2   = (const float*)d_in[15];
    const float* b2   = (const float*)d_in[16];
    const float* g1   = (const float*)d_in[17];
    const float* be1  = (const float*)d_in[18];
    const float* g2   = (const float*)d_in[19];
    const float* be2  = (const float*)d_in[20];
    const float* Wout = (const float*)d_in[21];
    const float* bout = (const float*)d_in[22];
    float* out = (float*)d_out;

    float *px, *pcomb, *pres, *pp2, *psp, *ph, *plo;
    cudaGetSymbolAddress((void**)&px,    g_x);
    cudaGetSymbolAddress((void**)&pcomb, g_comb);
    cudaGetSymbolAddress((void**)&pres,  g_res);
    cudaGetSymbolAddress((void**)&pp2,   g_p2);
    cudaGetSymbolAddress((void**)&psp,   g_sp);
    cudaGetSymbolAddress((void**)&ph,    g_h);
    cudaGetSymbolAddress((void**)&plo,   g_lo);

    cudaFuncSetAttribute(k_kvq_mma, cudaFuncAttributeMaxDynamicSharedMemorySize,
                         KVQ_SMEM);

    // weight transpose + bf16 3-split (all layers, q/k/v)
    k_convW<<<dim3(32,32,48), dim3(32,32)>>>(Wq, Wk, Wv);
    // embedding + pe (+ activation splits slot 0)
    k_embed<<<SBD/256, 256>>>(src, emb);

    for (int l=0; l<Ll; l++){
        int n = l + 1;                      // true source count
        int n_eff = (l == 0) ? 1 : l;       // deduped (srcs[0]==srcs[l] for l>=1)

        // Q + n_eff*K + n_eff*V projections on tensor pipe (bf16x3 emulation)
        k_kvq_mma<<<dim3(16,4,2*n_eff+1), 256, KVQ_SMEM>>>(bq + l*Dm, bk + l*Dm,
                                                           bv + l*Dm, l, n_eff);
        // attention scores, per (source, head)
        k_scores<<<dim3(4,4,n_eff*16), 256>>>(n_eff);
        // softmax over keys x layer-weight softmax (merged dup weight)
        k_softmax<<<n_eff*16*Sq/8, 256>>>(layer_w + l*(Ll+1), n, n_eff);
        // combine over (k, source)
        k_comb<<<dim3(2,4,16), 256>>>(n_eff);
        // output projection + residual, split-K=2 partials
        k_gemm_sk<<<dim3(16,8,2), 256>>>(pcomb, Wo + (size_t)l*Dm*Dm, bo + l*Dm,
                                         px, pres, pp2, Dm, Dm);
        // LN1 (sums both partials) -> new x
        k_ln<<<SB, 256>>>(pres, pp2, g1 + l*Dm, be1 + l*Dm, px, (float*)nullptr, -1);
        // SNN input current, split-K=2 partials
        k_gemm_sk<<<dim3(16,8,2), 256>>>(px, Wsnn + (size_t)l*Dm*Dm, bsnn + l*Dm,
                                         (const float*)nullptr, ph, pp2, Dm, Dm);
        // membrane scan -> spikes
        k_snn<<<Bsz, 1024>>>(ph, pp2, psp);
        // FF1 (relu)
        k_gemm<<<dim3(32,8), 256>>>(psp, W1 + (size_t)l*Dm*FFd, b1 + l*FFd,
                                    (const float*)nullptr, ph, FFd, Dm, 1, 0);
        // FF2 + residual, split-K=2 partials
        k_gemm_sk<<<dim3(16,8,2), 256>>>(ph, W2 + (size_t)l*FFd*Dm, b2 + l*Dm,
                                         px, pres, pp2, Dm, FFd);
        // LN2 -> new x, layer output, and bf16 splits into slot l+1
        k_ln<<<SB, 256>>>(pres, pp2, g2 + l*Dm, be2 + l*Dm, px,
                          plo + (size_t)l*SBD, l+1);
    }

    // final logits with transposed store into [B,S,V]
    k_gemm<<<dim3((Vv+63)/64, 8), 256>>>(px, Wout, bout, (const float*)nullptr,
                                         out, Vv, Dm, 0, 1);
}

// round 15
// speedup vs baseline: 1.5213x; 1.5213x over previous
#include <cuda_runtime.h>
#include <cuda_bf16.h>
#include <math.h>

// ---------------- problem constants ----------------
#define Bsz 2
#define Sq  256
#define Dm  1024
#define Hh  8
#define HDm 128
#define Ll  16
#define FFd 2048
#define Vv  50257
#define SB  (Sq*Bsz)       // 512 rows, row r = s*Bsz + b  ([S,B,*] layout)
#define SBD (SB*Dm)        // 524288
#define ATT_SCALE 0.08838834764831843f

// ---------------- device scratch (static allocations only) -----------------
__device__ float g_x[SBD];            // current x  [S,B,D]
__device__ float g_q[SBD];            // q proj
__device__ float g_k[Ll*SBD];         // k proj per (deduped) source
__device__ float g_v[Ll*SBD];         // v proj per source
__device__ float g_scores[Ll*16*Sq*Sq]; // [j][bh][q][k]
__device__ float g_comb[SBD];         // attention combine, partial group 0
__device__ float g_comb2[SBD];        // attention combine, partial group 1
__device__ float g_res[SBD];          // partial / residual sum pre-LN
__device__ float g_p2[SBD];           // second split-K partial
__device__ float g_sp[SBD];           // spikes
__device__ float g_h[SB*FFd];         // ff hidden / snn current (reused)
__device__ float g_lo[Ll*SBD];        // layer outputs

// ---------------- helpers ----------------
__device__ __forceinline__ float4 ldg4_guard(const float* p, int col, int N)
{
    float4 r;
    // vector load only if in-bounds AND 16B-aligned (Vv=50257 is odd!)
    if (col + 3 < N && ((((size_t)p) & 15) == 0)) {
        r = *(const float4*)(p);
    } else {
        r.x = (col+0<N)? p[0]:0.f; r.y = (col+1<N)? p[1]:0.f;
        r.z = (col+2<N)? p[2]:0.f; r.w = (col+3<N)? p[3]:0.f;
    }
    return r;
}

// k-major shared tiles: Ts[kk][row], row stride 68 floats (272B, 16B-aligned)
#define LDK 68

// inner product step: one LDS.128 per fragment, 16 scalar FFMA
#define MM16F(Abuf, Bbuf) \
  _Pragma("unroll") \
  for (int kk=0;kk<16;kk++){ \
    float4 a4 = *(const float4*)&Abuf[kk][ty<<2]; \
    float4 b4 = *(const float4*)&Bbuf[kk][tx<<2]; \
    acc[0][0]=fmaf(a4.x,b4.x,acc[0][0]); acc[0][1]=fmaf(a4.x,b4.y,acc[0][1]); \
    acc[0][2]=fmaf(a4.x,b4.z,acc[0][2]); acc[0][3]=fmaf(a4.x,b4.w,acc[0][3]); \
    acc[1][0]=fmaf(a4.y,b4.x,acc[1][0]); acc[1][1]=fmaf(a4.y,b4.y,acc[1][1]); \
    acc[1][2]=fmaf(a4.y,b4.z,acc[1][2]); acc[1][3]=fmaf(a4.y,b4.w,acc[1][3]); \
    acc[2][0]=fmaf(a4.z,b4.x,acc[2][0]); acc[2][1]=fmaf(a4.z,b4.y,acc[2][1]); \
    acc[2][2]=fmaf(a4.z,b4.z,acc[2][2]); acc[2][3]=fmaf(a4.z,b4.w,acc[2][3]); \
    acc[3][0]=fmaf(a4.w,b4.x,acc[3][0]); acc[3][1]=fmaf(a4.w,b4.y,acc[3][1]); \
    acc[3][2]=fmaf(a4.w,b4.z,acc[3][2]); acc[3][3]=fmaf(a4.w,b4.w,acc[3][3]); \
  }

// stage a row-major-loaded float4 (row arow, cols acol..acol+3) transposed
#define STAGE_T(T, buf, v) \
  T[buf][acol+0][arow]=v.x; T[buf][acol+1][arow]=v.y; \
  T[buf][acol+2][arow]=v.z; T[buf][acol+3][arow]=v.w;

// stage a k-row-loaded float4 (k row brow, cols bcol..+3) straight in
#define STAGE_K(T, buf, v) *(float4*)&T[buf][brow][bcol] = v;

// ---------------- generic tiled SGEMM core: C[M,N] = (A[+A2])[M,Kred]@B -----
// A row-major with leading dim lda (A2, if non-null, same layout, summed in
// staging); B row-major ldb=N (any N). M multiple of 64, Kred multiple of 16.
// 256 threads, 64x64 tile, double buffered.
__device__ __forceinline__ void gemm_core(
    const float* __restrict__ A, const float* __restrict__ A2, int lda,
    const float* __restrict__ Bw,
    const float* __restrict__ bias, const float* __restrict__ res,
    float* __restrict__ C, int N, int Kred, int relu, int store_T)
{
    __shared__ __align__(16) float As[2][16][LDK];
    __shared__ __align__(16) float Bs[2][16][LDK];
    const int tid = threadIdx.x;
    const int tx = tid & 15, ty = tid >> 4;
    const int m0 = blockIdx.y << 6, n0 = blockIdx.x << 6;
    const int arow = tid >> 2, acol = (tid & 3) << 2;
    const int brow = tid >> 4, bcol = (tid & 15) << 2;
    float acc[4][4];
#pragma unroll
    for (int i=0;i<4;i++)
#pragma unroll
        for (int j=0;j<4;j++) acc[i][j]=0.f;

    const float* Ap  = A  + (size_t)(m0 + arow) * lda + acol;
    const float* Ap2 = A2 ? A2 + (size_t)(m0 + arow) * lda + acol : nullptr;
    const int nk = Kred >> 4;
    float4 aR, bR;

    aR = *(const float4*)(Ap);
    if (Ap2){ float4 a2 = *(const float4*)(Ap2);
              aR.x+=a2.x; aR.y+=a2.y; aR.z+=a2.z; aR.w+=a2.w; }
    bR = ldg4_guard(Bw + (size_t)brow * N + n0 + bcol, n0 + bcol, N);
    STAGE_T(As, 0, aR); STAGE_K(Bs, 0, bR);
    __syncthreads();

    for (int kt = 1; kt < nk; kt++) {
        aR = *(const float4*)(Ap + kt*16);
        if (Ap2){ float4 a2 = *(const float4*)(Ap2 + kt*16);
                  aR.x+=a2.x; aR.y+=a2.y; aR.z+=a2.z; aR.w+=a2.w; }
        bR = ldg4_guard(Bw + (size_t)(kt*16 + brow) * N + n0 + bcol, n0 + bcol, N);
        const int cb = (kt-1)&1, nb = kt&1;
        MM16F(As[cb], Bs[cb]);
        STAGE_T(As, nb, aR); STAGE_K(Bs, nb, bR);
        __syncthreads();
    }
    { const int lb = (nk-1)&1; MM16F(As[lb], Bs[lb]); }

#pragma unroll
    for (int i=0;i<4;i++){
        int m = m0 + (ty<<2) + i;
#pragma unroll
        for (int j=0;j<4;j++){
            int nn = n0 + (tx<<2) + j;
            if (nn >= N) continue;
            float v = acc[i][j];
            if (bias) v += bias[nn];
            if (res)  v += res[(size_t)m*N + nn];
            if (relu) v = fmaxf(v, 0.f);
            if (!store_T) {
                C[(size_t)m*N + nn] = v;
            } else {                      // logits: row (s*B+b) -> out[b][s][v]
                int s = m >> 1, b = m & 1;
                C[(size_t)(b*Sq + s)*N + nn] = v;
            }
        }
    }
}

__global__ void k_gemm(const float* __restrict__ A, const float* __restrict__ Bw,
                       const float* __restrict__ bias, const float* __restrict__ res,
                       float* __restrict__ C, int N, int K, int relu, int store_T)
{
    gemm_core(A, nullptr, K, Bw, bias, res, C, N, K, relu, store_T);
}

// split-K=2: z=0 does k in [0,K/2) (+bias,+res) -> C0 ; z=1 does [K/2,K) -> C1
__global__ void k_gemm_sk(const float* __restrict__ A, const float* __restrict__ A2,
                          const float* __restrict__ Bw,
                          const float* __restrict__ bias, const float* __restrict__ res,
                          float* __restrict__ C0, float* __restrict__ C1, int N, int K)
{
    const int z = blockIdx.z;
    const int Kh = K >> 1;
    gemm_core(A + (size_t)z*Kh, A2 ? A2 + (size_t)z*Kh : nullptr, K,
              Bw + (size_t)z*Kh*N,
              z ? nullptr : bias, z ? nullptr : res,
              z ? C1 : C0, N, Kh, 0, 0);
}

// ---------------- batched Q/K/V projection: grid.z = 2*n_eff+1 -------------
__global__ void k_kvq(const float* __restrict__ Wq, const float* __restrict__ bq,
                      const float* __restrict__ Wk, const float* __restrict__ bk,
                      const float* __restrict__ Wv, const float* __restrict__ bv,
                      int n_eff)
{
    int z = blockIdx.z;
    const float *A, *W, *bi; float* C;
    if (z == 2*n_eff) { A = g_x; W = Wq; bi = bq; C = g_q; }
    else {
        int isv = (z >= n_eff) ? 1 : 0;
        int j = isv ? z - n_eff : z;
        A = (j == 0) ? g_x : g_lo + (size_t)(j-1)*SBD;
        W = isv ? Wv : Wk;
        bi = isv ? bv : bk;
        C = (isv ? g_v : g_k) + (size_t)j*SBD;
    }
    gemm_core(A, nullptr, Dm, W, bi, nullptr, C, Dm, Dm, 0, 0);
}

// ---------------- embedding + positional encoding ---------------------------
__global__ void k_embed(const int* __restrict__ src, const float* __restrict__ emb)
{
    int idx = blockIdx.x * 256 + threadIdx.x;       // over SBD
    int d = idx & (Dm-1);
    int r = idx >> 10;
    int b = r & 1, s = r >> 1;
    int tok = src[b*Sq + s];
    float v = emb[(size_t)tok*Dm + d] * 32.0f;      // sqrt(1024)
    int de = d & ~1;
    float ang = (float)s * expf((float)de * -0.008994473019508f); // -ln(1e4)/1024
    float pe = (d & 1) ? cosf(ang) : sinf(ang);
    g_x[idx] = v + pe;
}

// ---------------- scores: per (source j, head bh) NT-GEMM -------------------
__global__ void k_scores(int n_eff)
{
    __shared__ __align__(16) float Qs[2][16][LDK];
    __shared__ __align__(16) float Ks[2][16][LDK];
    const int tid = threadIdx.x;
    const int tx = tid & 15, ty = tid >> 4;
    const int arow = tid >> 2, acol = (tid & 3) << 2;
    const int z = blockIdx.z;                 // z = j*16 + bh
    const int bh = z & 15;
    const int b = bh >> 3, h = bh & 7;
    const int LDX = Bsz * Dm;                 // 2048
    const float* Aq = g_q + b*Dm + h*HDm;
    const float* Bk = g_k + (size_t)(z >> 4)*SBD + b*Dm + h*HDm;
    float* C = g_scores + (size_t)z * Sq * Sq;
    const int m0 = blockIdx.y << 6, n0 = blockIdx.x << 6;
    float acc[4][4];
#pragma unroll
    for (int i=0;i<4;i++)
#pragma unroll
        for (int j=0;j<4;j++) acc[i][j]=0.f;

    const float* Ap = Aq + (size_t)(m0 + arow) * LDX + acol;
    const float* Bp = Bk + (size_t)(n0 + arow) * LDX + acol;
    float4 qR, kR;

    qR = *(const float4*)(Ap);
    kR = *(const float4*)(Bp);
    STAGE_T(Qs, 0, qR); STAGE_T(Ks, 0, kR);
    __syncthreads();

    for (int kt = 1; kt < 8; kt++) {          // HD=128 -> 8 k-tiles
        qR = *(const float4*)(Ap + kt*16);
        kR = *(const float4*)(Bp + kt*16);
        const int cb = (kt-1)&1, nb = kt&1;
        MM16F(Qs[cb], Ks[cb]);
        STAGE_T(Qs, nb, qR); STAGE_T(Ks, nb, kR);
        __syncthreads();
    }
    MM16F(Qs[1], Ks[1]);

#pragma unroll
    for (int i=0;i<4;i++){
        int m = m0 + (ty<<2) + i;
#pragma unroll
        for (int j=0;j<4;j++){
            int nn = n0 + (tx<<2) + j;
            C[(size_t)m*Sq + nn] = acc[i][j] * ATT_SCALE;
        }
    }
}

// ------- softmax over keys x layer weight (dedup: src0 gets w0 + w_{n-1}) ---
__global__ void k_softmax(const float* __restrict__ lw, int n, int n_eff)
{
    int row  = blockIdx.x * 8 + (threadIdx.x >> 5);   // rows = n_eff*16*256
    int lane = threadIdx.x & 31;
    float* p = g_scores + (size_t)row * Sq;
    float x[8];
#pragma unroll
    for (int i=0;i<8;i++) x[i] = p[lane + (i<<5)];
    float mx = x[0];
#pragma unroll
    for (int i=1;i<8;i++) mx = fmaxf(mx, x[i]);
#pragma unroll
    for (int off=16;off>0;off>>=1) mx = fmaxf(mx, __shfl_xor_sync(0xffffffffu, mx, off));
    float sum = 0.f;
#pragma unroll
    for (int i=0;i<8;i++){ x[i] = expf(x[i]-mx); sum += x[i]; }
#pragma unroll
    for (int off=16;off>0;off>>=1) sum += __shfl_xor_sync(0xffffffffu, sum, off);
    int jj = row >> 12;                                // row / (16*256)
    float lm = -1e30f;
    for (int t=0;t<n;t++) lm = fmaxf(lm, lw[t]);
    float ls = 0.f;
    for (int t=0;t<n;t++) ls += expf(lw[t]-lm);
    float wj = expf(lw[jj]-lm) / ls;
    if (n > n_eff && jj == 0) wj += expf(lw[n-1]-lm) / ls;   // merged duplicate
    float sc = wj / sum;
#pragma unroll
    for (int i=0;i<8;i++) p[lane + (i<<5)] = x[i] * sc;
}

// ---------------- comb: per head, sum over sources; split into 2 groups -----
// grid.z = 32: z&15 = bh, z>>4 = source group (j = grp, grp+2, ...)
// group 0 -> g_comb, group 1 -> g_comb2 (summed by the O-projection staging)
__global__ void k_comb(int n_eff)
{
    __shared__ __align__(16) float As[2][16][LDK];
    __shared__ __align__(16) float Bs[2][16][LDK];
    const int tid = threadIdx.x;
    const int tx = tid & 15, ty = tid >> 4;
    const int arow = tid >> 2, acol = (tid & 3) << 2;
    const int brow = tid >> 4, bcol = (tid & 15) << 2;
    const int bh = blockIdx.z & 15, grp = blockIdx.z >> 4;
    const int b = bh >> 3, h = bh & 7;
    const int m0 = blockIdx.y << 6, n0 = blockIdx.x << 6;   // q tile, d tile
    float* Cout = grp ? g_comb2 : g_comb;
    float acc[4][4];
#pragma unroll
    for (int i=0;i<4;i++)
#pragma unroll
        for (int j=0;j<4;j++) acc[i][j]=0.f;

    for (int j=grp; j<n_eff; j+=2){
        const float* Aj = g_scores + (size_t)(j*16 + bh) * Sq * Sq;   // [q][k] ld=256
        const float* Vj = g_v + (size_t)j*SBD + b*Dm + h*HDm;          // [k][d] ld=2048
        const float* Ap = Aj + (size_t)(m0 + arow) * Sq + acol;
        float4 aR, bR;
        aR = *(const float4*)(Ap);
        bR = *(const float4*)(Vj + (size_t)brow*2048 + n0 + bcol);
        STAGE_T(As, 0, aR); STAGE_K(Bs, 0, bR);
        __syncthreads();
        for (int kt = 1; kt < 16; kt++) {     // Sq=256 -> 16 k-tiles
            aR = *(const float4*)(Ap + kt*16);
            bR = *(const float4*)(Vj + (size_t)(kt*16+brow)*2048 + n0 + bcol);
            const int cb = (kt-1)&1, nb = kt&1;
            MM16F(As[cb], Bs[cb]);
            STAGE_T(As, nb, aR); STAGE_K(Bs, nb, bR);
            __syncthreads();
        }
        MM16F(As[1], Bs[1]);
        __syncthreads();                      // buffers reused by next source
    }

#pragma unroll
    for (int i=0;i<4;i++){
        int q = m0 + (ty<<2) + i;
        int r = q*Bsz + b;
#pragma unroll
        for (int j=0;j<4;j++){
            int d = h*HDm + n0 + (tx<<2) + j;
            Cout[(size_t)r*Dm + d] = acc[i][j];
        }
    }
}

// ------- layernorm over D of (in [+ in2]), write out (and optional copy) ----
__global__ void k_ln(const float* __restrict__ in, const float* __restrict__ in2,
                     const float* __restrict__ g, const float* __restrict__ be,
                     float* __restrict__ out, float* __restrict__ out2)
{
    __shared__ float s1[8], s2[8];
    __shared__ float smean, srstd;
    int r = blockIdx.x, tid = threadIdx.x;
    int lane = tid & 31, wid = tid >> 5;
    const float* row  = in  + (size_t)r*Dm;
    const float* row2 = in2 ? in2 + (size_t)r*Dm : nullptr;
    float v[4], sum = 0.f, sq = 0.f;
#pragma unroll
    for (int i=0;i<4;i++){
        float t = row[tid + (i<<8)];
        if (row2) t += row2[tid + (i<<8)];
        v[i] = t; sum += t; sq += t*t;
    }
#pragma unroll
    for (int off=16;off>0;off>>=1){
        sum += __shfl_xor_sync(0xffffffffu, sum, off);
        sq  += __shfl_xor_sync(0xffffffffu, sq,  off);
    }
    if (lane == 0){ s1[wid] = sum; s2[wid] = sq; }
    __syncthreads();
    if (tid == 0){
        float a=0.f, c=0.f;
        for (int i=0;i<8;i++){ a += s1[i]; c += s2[i]; }
        float mean = a * (1.f/1024.f);
        float var  = c * (1.f/1024.f) - mean*mean;
        smean = mean; srstd = rsqrtf(var + 1e-5f);
    }
    __syncthreads();
    float mean = smean, rstd = srstd;
#pragma unroll
    for (int i=0;i<4;i++){
        int d = tid + (i<<8);
        float o = (v[i]-mean)*rstd*g[d] + be[d];
        out[(size_t)r*Dm + d] = o;
        if (out2) out2[(size_t)r*Dm + d] = o;
    }
}

// ---------------- SNN scan: one block per batch, 1024 threads ---------------
// current = cur + cur2 (two split-K partials)
__global__ void k_snn(const float* __restrict__ cur, const float* __restrict__ cur2,
                      float* __restrict__ sp)
{
    __shared__ float red[32];
    __shared__ float redt;
    int b = blockIdx.x, d = threadIdx.x;
    int lane = d & 31, wid = d >> 5;
    float mem = 0.f, thr = 1.0f;
    size_t i0 = (size_t)b*Dm + d;
    float nxt = cur[i0] + cur2[i0];                  // t = 0 row = (0*B+b)
    for (int t=0;t<Sq;t++){
        float cin = nxt;
        if (t+1 < Sq){
            size_t ix = (size_t)((t+1)*Bsz + b)*Dm + d;
            nxt = cur[ix] + cur2[ix];
        }
        float v = mem;
#pragma unroll
        for (int off=16;off>0;off>>=1) v += __shfl_xor_sync(0xffffffffu, v, off);
        if (lane == 0) red[wid] = v;
        __syncthreads();
        if (wid == 0){
            float u = red[lane];
#pragma unroll
            for (int off=16;off>0;off>>=1) u += __shfl_xor_sync(0xffffffffu, u, off);
            if (lane == 0) redt = u;
        }
        __syncthreads();
        float c = cin - 0.1f * redt;
        mem = 0.9f * mem + c;
        float s = (mem >= thr) ? 1.f : 0.f;
        mem -= s * thr;
        thr = 0.9f * thr + 0.1f * s;
        sp[(size_t)(t*Bsz + b)*Dm + d] = s;
    }
}

// ---------------- host orchestration ----------------------------------------
extern "C" void kernel_launch(void* const* d_in, const int* in_sizes, int n_in,
                              void* d_out, int out_size)
{
    const int*   src  = (const int*)  d_in[0];
    const float* emb  = (const float*)d_in[1];
    const float* Wq   = (const float*)d_in[2];
    const float* bq   = (const float*)d_in[3];
    const float* Wk   = (const float*)d_in[4];
    const float* bk   = (const float*)d_in[5];
    const float* Wv   = (const float*)d_in[6];
    const float* bv   = (const float*)d_in[7];
    const float* Wo   = (const float*)d_in[8];
    const float* bo   = (const float*)d_in[9];
    const float* layer_w = (const float*)d_in[10];
    const float* Wsnn = (const float*)d_in[11];
    const float* bsnn = (const float*)d_in[12];
    const float* W1   = (const float*)d_in[13];
    const float* b1   = (const float*)d_in[14];
    const float* W2   = (const float*)d_in[15];
    const float* b2   = (const float*)d_in[16];
    const float* g1   = (const float*)d_in[17];
    const float* be1  = (const float*)d_in[18];
    const float* g2   = (const float*)d_in[19];
    const float* be2  = (const float*)d_in[20];
    const float* Wout = (const float*)d_in[21];
    const float* bout = (const float*)d_in[22];
    float* out = (float*)d_out;

    float *px, *pcomb, *pcomb2, *pres, *pp2, *psp, *ph, *plo;
    cudaGetSymbolAddress((void**)&px,     g_x);
    cudaGetSymbolAddress((void**)&pcomb,  g_comb);
    cudaGetSymbolAddress((void**)&pcomb2, g_comb2);
    cudaGetSymbolAddress((void**)&pres,   g_res);
    cudaGetSymbolAddress((void**)&pp2,    g_p2);
    cudaGetSymbolAddress((void**)&psp,    g_sp);
    cudaGetSymbolAddress((void**)&ph,     g_h);
    cudaGetSymbolAddress((void**)&plo,    g_lo);

    k_embed<<<SBD/256, 256>>>(src, emb);

    for (int l=0; l<Ll; l++){
        int n = l + 1;                      // true source count
        int n_eff = (l == 0) ? 1 : l;       // deduped (srcs[0]==srcs[l] for l>=1)
        const float* Wql = Wq + (size_t)l*Dm*Dm;
        const float* Wkl = Wk + (size_t)l*Dm*Dm;
        const float* Wvl = Wv + (size_t)l*Dm*Dm;

        // Q + n_eff*K + n_eff*V projections, batched over grid.z
        k_kvq<<<dim3(16,8,2*n_eff+1), 256>>>(Wql, bq + l*Dm, Wkl, bk + l*Dm,
                                             Wvl, bv + l*Dm, n_eff);
        // attention scores, per (source, head)
        k_scores<<<dim3(4,4,n_eff*16), 256>>>(n_eff);
        // softmax over keys x layer-weight softmax (merged dup weight)
        k_softmax<<<n_eff*16*Sq/8, 256>>>(layer_w + l*(Ll+1), n, n_eff);
        // combine over (k, source), split into 2 source groups -> 256 CTAs
        k_comb<<<dim3(2,4,32), 256>>>(n_eff);
        // output projection (A = comb + comb2) + residual, split-K=2 partials
        k_gemm_sk<<<dim3(16,8,2), 256>>>(pcomb, pcomb2, Wo + (size_t)l*Dm*Dm,
                                         bo + l*Dm, px, pres, pp2, Dm, Dm);
        // LN1 (sums both partials) -> new x
        k_ln<<<SB, 256>>>(pres, pp2, g1 + l*Dm, be1 + l*Dm, px, (float*)nullptr);
        // SNN input current, split-K=2 partials
        k_gemm_sk<<<dim3(16,8,2), 256>>>(px, (const float*)nullptr,
                                         Wsnn + (size_t)l*Dm*Dm, bsnn + l*Dm,
                                         (const float*)nullptr, ph, pp2, Dm, Dm);
        // membrane scan -> spikes
        k_snn<<<Bsz, 1024>>>(ph, pp2, psp);
        // FF1 (relu)
        k_gemm<<<dim3(32,8), 256>>>(psp, W1 + (size_t)l*Dm*FFd, b1 + l*FFd,
                                    (const float*)nullptr, ph, FFd, Dm, 1, 0);
        // FF2 + residual, split-K=2 partials
        k_gemm_sk<<<dim3(16,8,2), 256>>>(ph, (const float*)nullptr,
                                         W2 + (size_t)l*FFd*Dm, b2 + l*Dm,
                                         px, pres, pp2, Dm, FFd);
        // LN2 (sums partials) -> new x, also store as this layer's output
        k_ln<<<SB, 256>>>(pres, pp2, g2 + l*Dm, be2 + l*Dm, px, plo + (size_t)l*SBD);
    }

    // final logits with transposed store into [B,S,V]
    k_gemm<<<dim3((Vv+63)/64, 8), 256>>>(px, Wout, bout, (const float*)nullptr,
                                         out, Vv, Dm, 0, 1);
}